// round 6
// baseline (speedup 1.0000x reference)
#include <cuda_runtime.h>
#include <cuda_fp16.h>
#include <cstdint>

#define BB 8
#define NC 2048
#define YD 8
#define GR 128
#define MM (GR*GR)
#define KC 64            // K per chunk (64 halfs = 128B rows)
#define NCHK (NC/KC)     // 32 chunks (full K per tile)
#define NTILE 144        // 8b * 9ych * 2ixh

// ---- device scratch ----
__device__ __half g_w[2][BB][GR][NC];    // [axis(0=x,1=y)][b][row][n]
__device__ __half g_yl[BB][YD + 1][NC];  // [b][ych][n], ych 0 -> 1.0
__device__ float  g_s[BB][YD + 1][MM];   // unnormalized GEMM output
__device__ unsigned g_bar;               // monotonic ticket barrier counter

// ---- helpers ----
__device__ __forceinline__ float ex2f(float x) {
    float y; asm("ex2.approx.f32 %0, %1;" : "=f"(y) : "f"(x)); return y;
}
__device__ __forceinline__ float rcpf(float x) {
    float y; asm("rcp.approx.f32 %0, %1;" : "=f"(y) : "f"(x)); return y;
}
__device__ __forceinline__ uint32_t s2u(const void* p) {
    uint32_t a;
    asm("{ .reg .u64 t; cvta.to.shared.u64 t, %1; cvt.u32.u64 %0, t; }" : "=r"(a) : "l"(p));
    return a;
}
__device__ __forceinline__ uint32_t hmul2u(uint32_t a, uint32_t b) {
    __half2 r = __hmul2(*(__half2*)&a, *(__half2*)&b);
    return *(uint32_t*)&r;
}
// pack two f32 -> f16x2; first asm source = HIGH half
__device__ __forceinline__ uint32_t pkh2(float hi, float lo) {
    uint32_t r;
    asm("cvt.rn.f16x2.f32 %0, %1, %2;" : "=r"(r) : "f"(hi), "f"(lo));
    return r;
}
#define STS128(addr, v) \
    asm volatile("st.shared.v4.b32 [%0], {%1, %2, %3, %4};" \
                 :: "r"(addr), "r"((v).x), "r"((v).y), "r"((v).z), "r"((v).w) : "memory")

__device__ __forceinline__ void ldm4(uint32_t* r, uint32_t addr) {
    asm volatile("ldmatrix.sync.aligned.m8n8.x4.shared.b16 {%0,%1,%2,%3}, [%4];"
        : "=r"(r[0]), "=r"(r[1]), "=r"(r[2]), "=r"(r[3]) : "r"(addr));
}
__device__ __forceinline__ void mma16816(float* d, const uint32_t* a, const uint32_t* bf) {
    asm volatile("mma.sync.aligned.m16n8k16.row.col.f32.f16.f16.f32 "
        "{%0,%1,%2,%3}, {%4,%5,%6,%7}, {%8,%9}, {%0,%1,%2,%3};"
        : "+f"(d[0]), "+f"(d[1]), "+f"(d[2]), "+f"(d[3])
        : "r"(a[0]), "r"(a[1]), "r"(a[2]), "r"(a[3]), "r"(bf[0]), "r"(bf[1]));
}

// Grid-wide barrier: all CTAs co-resident (grid == #SMs, 1 CTA/SM).
// Monotonic ticket counter -> no reset -> safe across CUDA-graph replays.
__device__ __forceinline__ void grid_barrier() {
    __syncthreads();
    if (threadIdx.x == 0) {
        __threadfence();
        unsigned t = atomicAdd(&g_bar, 1u);
        unsigned target = (t / gridDim.x + 1u) * gridDim.x;
        while (*(volatile unsigned*)&g_bar < target) { }
        __threadfence();
    }
    __syncthreads();
}

// SMEM buffer offsets for gemm phase
#define SA0 0
#define SA1 16384
#define SB0 32768
#define SB1 40960

__global__ void __launch_bounds__(256)
rbf_fused(const float* __restrict__ xc, const float* __restrict__ yc,
          const float* __restrict__ gp, const float* __restrict__ sigma,
          float* __restrict__ out)
{
    __shared__ __align__(1024) char smem[49152];
    const uint32_t sb = s2u(smem);
    const int tid = threadIdx.x;
    const int nsm = gridDim.x;

    // ================= Phase A: precompute weights + lifted y =================
    {
        const float sg = sigma[0];
        const float cc = -0.5f * 1.4426950408889634f / (sg * sg);
        float* sg_g   = (float*)smem;         // [16] grid coords
        float* sg_c2  = (float*)smem + 16;    // [16] cc*g^2

        for (int u = blockIdx.x; u < 800; u += nsm) {
            if (u < 512) {
                // weights unit: axis, b, rowgroup(16 rows), nsplit(512 n)
                const int axis = u >> 8;
                const int b    = (u >> 5) & 7;
                const int rg   = (u >> 2) & 7;
                const int ns   = u & 3;
                __syncthreads();
                if (tid < 16) {
                    const int row = rg * 16 + tid;
                    const float g = (axis == 0) ? gp[2 * row] : gp[2 * (row * GR) + 1];
                    sg_g[tid]  = g;
                    sg_c2[tid] = cc * g * g;
                }
                __syncthreads();

                const int n0 = ns * 512 + tid * 2;
                const float4 xv = ((const float4*)xc)[((size_t)b * NC + n0) >> 1];
                const float c0 = axis ? xv.y : xv.x;
                const float c1 = axis ? xv.w : xv.z;
                const float a0_0 = cc * c0 * c0, a1_0 = -2.0f * cc * c0;
                const float a0_1 = cc * c1 * c1, a1_1 = -2.0f * cc * c1;
#pragma unroll
                for (int rr = 0; rr < 16; rr++) {
                    const float g = sg_g[rr], c2 = sg_c2[rr];
                    const float e0 = ex2f(fmaf(a1_0, g, a0_0 + c2));
                    const float e1 = ex2f(fmaf(a1_1, g, a0_1 + c2));
                    *(uint32_t*)&g_w[axis][b][rg * 16 + rr][n0] = pkh2(e1, e0);
                }
            } else {
                // yl unit: b, ych, nsplit(512 n)
                const int r   = u - 512;       // 288 units = 8 * 9 * 4
                const int b   = r / 36;
                const int rr  = r % 36;
                const int ych = rr >> 2;
                const int ns  = rr & 3;
                const int n0  = ns * 512 + tid * 2;
                uint32_t v;
                if (ych == 0) {
                    v = 0x3C003C00u;           // {1.0h, 1.0h}
                } else {
                    const float y0 = yc[((size_t)b * NC + n0) * YD + (ych - 1)];
                    const float y1 = yc[((size_t)b * NC + n0 + 1) * YD + (ych - 1)];
                    v = pkh2(y1, y0);
                }
                *(uint32_t*)&g_yl[b][ych][n0] = v;
            }
        }
    }

    grid_barrier();

    // ================= Phase B: GEMM (mma.sync, double-buffered) =================
    {
        const int wid  = tid >> 5;
        const int lane = tid & 31;
        const int warp_m = wid >> 1;
        const int warp_n = wid & 1;

        const int col8 = tid & 7;
        const int row0 = tid >> 3;
        uint32_t swA[4], swB[2];
#pragma unroll
        for (int rr = 0; rr < 4; rr++) {
            const uint32_t off = (uint32_t)(row0 + 32 * rr) * 128u + (uint32_t)col8 * 16u;
            swA[rr] = off ^ ((off >> 3) & 0x70);
        }
#pragma unroll
        for (int rr = 0; rr < 2; rr++) {
            const uint32_t off = (uint32_t)(row0 + 32 * rr) * 128u + (uint32_t)col8 * 16u;
            swB[rr] = off ^ ((off >> 3) & 0x70);
        }
        uint32_t roA[2], xoA[2];
#pragma unroll
        for (int f = 0; f < 2; f++) {
            const uint32_t rA = warp_m * 32 + f * 16 + (lane & 15);
            roA[f] = rA * 128u;
            xoA[f] = (rA & 7) << 4;
        }
        const uint32_t subA = ((lane >> 4) & 1) * 16u;
        uint32_t roB[2], xoB[2];
#pragma unroll
        for (int gp2 = 0; gp2 < 2; gp2++) {
            const uint32_t rB = warp_n * 32 + gp2 * 16 + ((lane >> 4) & 1) * 8 + (lane & 7);
            roB[gp2] = rB * 128u;
            xoB[gp2] = (rB & 7) << 4;
        }
        const uint32_t subB = ((lane >> 3) & 1) * 16u;

        for (int t = blockIdx.x; t < NTILE; t += nsm) {
            const int b   = t / 18;
            const int r   = t % 18;
            const int ych = r >> 1;
            const int ixh = r & 1;

            const uint4* __restrict__ apw = (const uint4*)&g_w[1][b][0][0];
            const uint4* __restrict__ bpw = (const uint4*)&g_w[0][b][ixh * 64][0];
            const __half* __restrict__ ylp = &g_yl[b][ych][0];

            float acc[2][4][4];
#pragma unroll
            for (int f = 0; f < 2; f++)
#pragma unroll
                for (int g = 0; g < 4; g++)
#pragma unroll
                    for (int e = 0; e < 4; e++) acc[f][g][e] = 0.0f;

            uint4 ra[4], rb[2], ryl;
            auto ldregs = [&](int c) {
                const int k0 = c * KC + col8 * 8;
#pragma unroll
                for (int rr = 0; rr < 4; rr++) ra[rr] = apw[((row0 + 32 * rr) * NC + k0) >> 3];
#pragma unroll
                for (int rr = 0; rr < 2; rr++) rb[rr] = bpw[((row0 + 32 * rr) * NC + k0) >> 3];
                ryl = *(const uint4*)(ylp + k0);
            };
            auto stage = [&](int p) {
                const uint32_t abase = sb + (p ? SA1 : SA0);
                const uint32_t bbase = sb + (p ? SB1 : SB0);
#pragma unroll
                for (int rr = 0; rr < 4; rr++) {
                    uint4 v;
                    v.x = hmul2u(ra[rr].x, ryl.x);
                    v.y = hmul2u(ra[rr].y, ryl.y);
                    v.z = hmul2u(ra[rr].z, ryl.z);
                    v.w = hmul2u(ra[rr].w, ryl.w);
                    STS128(abase + swA[rr], v);
                }
#pragma unroll
                for (int rr = 0; rr < 2; rr++) STS128(bbase + swB[rr], rb[rr]);
            };

            __syncthreads();          // smem safe to reuse (prior tile / phase done)
            ldregs(0);
            stage(0);
            ldregs(1);
            __syncthreads();

            for (int c = 0; c < NCHK; c++) {
                const int p = c & 1;
                if (c + 1 < NCHK) stage(1 - p);
                if (c + 2 < NCHK) ldregs(c + 2);

                const uint32_t aB = sb + (p ? SA1 : SA0);
                const uint32_t bB = sb + (p ? SB1 : SB0);
#pragma unroll
                for (int s = 0; s < 4; s++) {
                    uint32_t afr[2][4], bfr[4][2];
#pragma unroll
                    for (int f = 0; f < 2; f++)
                        ldm4(afr[f], aB + roA[f] + (((uint32_t)(s * 32) + subA) ^ xoA[f]));
#pragma unroll
                    for (int gp2 = 0; gp2 < 2; gp2++) {
                        uint32_t tt[4];
                        ldm4(tt, bB + roB[gp2] + (((uint32_t)(s * 32) + subB) ^ xoB[gp2]));
                        bfr[gp2 * 2 + 0][0] = tt[0]; bfr[gp2 * 2 + 0][1] = tt[1];
                        bfr[gp2 * 2 + 1][0] = tt[2]; bfr[gp2 * 2 + 1][1] = tt[3];
                    }
#pragma unroll
                    for (int f = 0; f < 2; f++)
#pragma unroll
                        for (int g = 0; g < 4; g++)
                            mma16816(acc[f][g], afr[f], bfr[g]);
                }
                __syncthreads();
            }

            float* dst = &g_s[b][ych][0];
            const int cbase = ixh * 64 + warp_n * 32 + (lane & 3) * 2;
            const int rlo = (lane >> 2);
#pragma unroll
            for (int f = 0; f < 2; f++) {
                const int rowb = warp_m * 32 + f * 16 + rlo;
#pragma unroll
                for (int g = 0; g < 4; g++) {
                    const int cc2 = cbase + g * 8;
                    *(float2*)(dst + (size_t)rowb * GR + cc2)       = make_float2(acc[f][g][0], acc[f][g][1]);
                    *(float2*)(dst + (size_t)(rowb + 8) * GR + cc2) = make_float2(acc[f][g][2], acc[f][g][3]);
                }
            }
        }
    }

    grid_barrier();

    // ================= Phase C: combine / normalize =================
    {
        const int total = BB * (YD + 1) * (MM / 4);      // 294912 float4 items
        for (int idx = blockIdx.x * 256 + tid; idx < total; idx += nsm * 256) {
            const int b  = idx / ((YD + 1) * (MM / 4));
            const int rr = idx % ((YD + 1) * (MM / 4));
            const int ch = rr >> 12;
            const int m4 = (rr & 4095) * 4;

            const float4 dv = *(const float4*)&g_s[b][0][m4];
            float* op = out + ((size_t)b * (YD + 1) + ch) * MM + m4;
            if (ch == 0) {
                *(float4*)op = dv;
            } else {
                float4 a = *(const float4*)&g_s[b][ch][m4];
                a.x *= rcpf(dv.x + 1e-5f);
                a.y *= rcpf(dv.y + 1e-5f);
                a.z *= rcpf(dv.z + 1e-5f);
                a.w *= rcpf(dv.w + 1e-5f);
                *(float4*)op = a;
            }
        }
    }
}

extern "C" void kernel_launch(void* const* d_in, const int* in_sizes, int n_in,
                              void* d_out, int out_size)
{
    const float* xc    = (const float*)d_in[0];  // (8, 2048, 2)
    const float* yc    = (const float*)d_in[1];  // (8, 2048, 8)
    const float* gp    = (const float*)d_in[2];  // (1, 16384, 2)
    const float* sigma = (const float*)d_in[3];  // scalar
    float* out = (float*)d_out;                  // (8, 9, 128, 128)

    int nsm = 148;
    cudaDeviceGetAttribute(&nsm, cudaDevAttrMultiProcessorCount, 0);
    rbf_fused<<<nsm, 256>>>(xc, yc, gp, sigma, out);
}

// round 7
// speedup vs baseline: 1.3278x; 1.3278x over previous
#include <cuda_runtime.h>
#include <cuda_fp16.h>
#include <cstdint>

#define BB 8
#define NC 2048
#define YD 8
#define GR 128
#define MM (GR*GR)
#define KC 64            // K per chunk (64 halfs = 128B rows)
#define KSPL 4           // K split across CTAs
#define KPER (NC/KSPL)   // 512
#define NCHK (KPER/KC)   // 8 chunks per CTA
#define STAGE 32768      // A(16KB) + B(16KB) per pipeline stage
#define NSTAGE 3

// ---- device scratch ----
__device__ __half g_w[2][BB][GR][NC];        // [axis(0=x,1=y)][b][row][n]
__device__ __half g_yl[BB][YD + 1][NC];      // [b][ych][n], ych 0 -> 1.0
__device__ float  g_s[KSPL][BB][YD + 1][MM]; // partial GEMM outputs

// ---- helpers ----
__device__ __forceinline__ float ex2f(float x) {
    float y; asm("ex2.approx.f32 %0, %1;" : "=f"(y) : "f"(x)); return y;
}
__device__ __forceinline__ float rcpf(float x) {
    float y; asm("rcp.approx.f32 %0, %1;" : "=f"(y) : "f"(x)); return y;
}
__device__ __forceinline__ uint32_t s2u(const void* p) {
    uint32_t a;
    asm("{ .reg .u64 t; cvta.to.shared.u64 t, %1; cvt.u32.u64 %0, t; }" : "=r"(a) : "l"(p));
    return a;
}
__device__ __forceinline__ uint32_t hmul2u(uint32_t a, uint32_t b) {
    __half2 r = __hmul2(*(__half2*)&a, *(__half2*)&b);
    return *(uint32_t*)&r;
}
__device__ __forceinline__ uint32_t pkh2(float hi, float lo) {
    uint32_t r;
    asm("cvt.rn.f16x2.f32 %0, %1, %2;" : "=r"(r) : "f"(hi), "f"(lo));
    return r;
}
__device__ __forceinline__ void cpasync16(uint32_t dst, const void* src) {
    asm volatile("cp.async.cg.shared.global [%0], [%1], 16;" :: "r"(dst), "l"(src) : "memory");
}
#define CP_COMMIT() asm volatile("cp.async.commit_group;" ::: "memory")
#define CP_WAIT1()  asm volatile("cp.async.wait_group 1;" ::: "memory")
#define CP_WAIT0()  asm volatile("cp.async.wait_group 0;" ::: "memory")

__device__ __forceinline__ void ldm4(uint32_t* r, uint32_t addr) {
    asm volatile("ldmatrix.sync.aligned.m8n8.x4.shared.b16 {%0,%1,%2,%3}, [%4];"
        : "=r"(r[0]), "=r"(r[1]), "=r"(r[2]), "=r"(r[3]) : "r"(addr));
}
__device__ __forceinline__ void mma16816(float* d, const uint32_t* a, const uint32_t* bf) {
    asm volatile("mma.sync.aligned.m16n8k16.row.col.f32.f16.f16.f32 "
        "{%0,%1,%2,%3}, {%4,%5,%6,%7}, {%8,%9}, {%0,%1,%2,%3};"
        : "+f"(d[0]), "+f"(d[1]), "+f"(d[2]), "+f"(d[3])
        : "r"(a[0]), "r"(a[1]), "r"(a[2]), "r"(a[3]), "r"(bf[0]), "r"(bf[1]));
}

// =====================  precompute (weights + lifted y)  =====================
// grid = 400: [0,256) weights (axis,b,rowgroup,ns2); [256,400) yl (b,ych,ns2)
__global__ void __launch_bounds__(256)
pre_all(const float* __restrict__ xc, const float* __restrict__ yc,
        const float* __restrict__ gp, const float* __restrict__ sigma)
{
    const int bx = blockIdx.x;
    if (bx < 256) {
        const int axis = bx >> 7;
        const int b    = (bx >> 4) & 7;
        const int rg   = (bx >> 1) & 7;
        const int ns   = bx & 1;
        const float sg = sigma[0];
        const float cc = -0.5f * 1.4426950408889634f / (sg * sg);

        __shared__ float sg_g[16], sg_c2[16];
        if (threadIdx.x < 16) {
            const int row = rg * 16 + threadIdx.x;
            const float g = (axis == 0) ? gp[2 * row] : gp[2 * (row * GR) + 1];
            sg_g[threadIdx.x]  = g;
            sg_c2[threadIdx.x] = cc * g * g;
        }
        __syncthreads();

        const int n0 = ns * 1024 + threadIdx.x * 4;
        const float4 xv01 = ((const float4*)xc)[((size_t)b * NC + n0) >> 1];
        const float4 xv23 = ((const float4*)xc)[(((size_t)b * NC + n0) >> 1) + 1];
        const float c0 = axis ? xv01.y : xv01.x;
        const float c1 = axis ? xv01.w : xv01.z;
        const float c2v = axis ? xv23.y : xv23.x;
        const float c3 = axis ? xv23.w : xv23.z;
        const float a00 = cc * c0 * c0,  a10 = -2.0f * cc * c0;
        const float a01 = cc * c1 * c1,  a11 = -2.0f * cc * c1;
        const float a02 = cc * c2v * c2v, a12 = -2.0f * cc * c2v;
        const float a03 = cc * c3 * c3,  a13 = -2.0f * cc * c3;
#pragma unroll
        for (int rr = 0; rr < 16; rr++) {
            const float g = sg_g[rr], k2 = sg_c2[rr];
            const float e0 = ex2f(fmaf(a10, g, a00 + k2));
            const float e1 = ex2f(fmaf(a11, g, a01 + k2));
            const float e2 = ex2f(fmaf(a12, g, a02 + k2));
            const float e3 = ex2f(fmaf(a13, g, a03 + k2));
            uint2 v; v.x = pkh2(e1, e0); v.y = pkh2(e3, e2);
            *(uint2*)&g_w[axis][b][rg * 16 + rr][n0] = v;
        }
    } else {
        const int r   = bx - 256;        // 144 = 8 * 9 * 2
        const int b   = r / 18;
        const int rr  = r % 18;
        const int ych = rr >> 1;
        const int ns  = rr & 1;
        const int n0  = ns * 1024 + threadIdx.x * 4;
        uint2 v;
        if (ych == 0) {
            v.x = 0x3C003C00u; v.y = 0x3C003C00u;
        } else {
            const float* yb = yc + ((size_t)b * NC + n0) * YD + (ych - 1);
            v.x = pkh2(yb[8],  yb[0]);
            v.y = pkh2(yb[24], yb[16]);
        }
        *(uint2*)&g_yl[b][ych][n0] = v;
    }
}

// =====================  main GEMM: 128x128 tile, cp.async 3-stage  =====================
// CTA = (b, ych, ks). D[iy 0..127][ix 0..127] = sum_{n in Kslice} (yl[n]*wy[n,iy])*wx[n,ix]
__global__ void __launch_bounds__(256, 2)
rbf_gemm()
{
    extern __shared__ __align__(1024) char smem[];
    const uint32_t sb = s2u(smem);

    const int tid  = threadIdx.x;
    const int wid  = tid >> 5;
    const int lane = tid & 31;
    const int warp_m = wid >> 1;     // 0..3 (m32 each)
    const int warp_n = wid & 1;      // 0..1 (n64 each)

    const int bx  = blockIdx.x;      // 288 = 8 * 9 * 4
    const int b   = bx / 36;
    const int r   = bx % 36;
    const int ych = r >> 2;
    const int ks  = r & 3;

    // ---- cp.async staging maps (per thread: 4 A rows + 4 B rows, 16B each) ----
    const int col8 = tid & 7;
    const int row0 = tid >> 3;       // 0..31
    uint32_t sw[4];
#pragma unroll
    for (int rr = 0; rr < 4; rr++) {
        const uint32_t off = (uint32_t)(row0 + 32 * rr) * 128u + (uint32_t)col8 * 16u;
        sw[rr] = off ^ ((off >> 3) & 0x70);
    }
    const char* aR[4];
    const char* bR[4];
#pragma unroll
    for (int rr = 0; rr < 4; rr++) {
        aR[rr] = (const char*)&g_w[1][b][row0 + 32 * rr][ks * KPER + col8 * 8];
        bR[rr] = (const char*)&g_w[0][b][row0 + 32 * rr][ks * KPER + col8 * 8];
    }

    auto cp_stage = [&](int c, int st) {
        const uint32_t base = sb + (uint32_t)st * STAGE;
        const int boff = c * 128;    // 64 halfs per chunk
#pragma unroll
        for (int rr = 0; rr < 4; rr++) cpasync16(base + sw[rr], aR[rr] + boff);
#pragma unroll
        for (int rr = 0; rr < 4; rr++) cpasync16(base + 16384u + sw[rr], bR[rr] + boff);
    };

    // ---- ldmatrix address components (stage-relative) ----
    uint32_t roA[2], xoA[2];
#pragma unroll
    for (int f = 0; f < 2; f++) {
        const uint32_t rA = warp_m * 32 + f * 16 + (lane & 15);
        roA[f] = rA * 128u;
        xoA[f] = (rA & 7) << 4;
    }
    const uint32_t subA = ((lane >> 4) & 1) * 16u;
    uint32_t roB[4], xoB[4];
#pragma unroll
    for (int gp2 = 0; gp2 < 4; gp2++) {
        const uint32_t rB = warp_n * 64 + gp2 * 16 + ((lane >> 4) & 1) * 8 + (lane & 7);
        roB[gp2] = 16384u + rB * 128u;
        xoB[gp2] = (rB & 7) << 4;
    }
    const uint32_t subB = ((lane >> 3) & 1) * 16u;

    const __half* __restrict__ ylp = &g_yl[b][ych][ks * KPER];
    const uint32_t ylo = (lane & 3) * 2;

    float acc[2][8][4];
#pragma unroll
    for (int f = 0; f < 2; f++)
#pragma unroll
        for (int g = 0; g < 8; g++)
#pragma unroll
            for (int e = 0; e < 4; e++) acc[f][g][e] = 0.0f;

    // ---- 3-stage pipeline prologue ----
    cp_stage(0, 0); CP_COMMIT();
    cp_stage(1, 1); CP_COMMIT();

    for (int k = 0; k < NCHK; k++) {
        if (k == NCHK - 1) { CP_WAIT0(); } else { CP_WAIT1(); }
        __syncthreads();                       // chunk k visible; stage (k+2)%3 free
        if (k + 2 < NCHK) { cp_stage(k + 2, (k + 2) % 3); CP_COMMIT(); }

        const uint32_t stb = sb + (uint32_t)(k % 3) * STAGE;
#pragma unroll
        for (int s = 0; s < 4; s++) {
            uint32_t afr[2][4];
#pragma unroll
            for (int f = 0; f < 2; f++)
                ldm4(afr[f], stb + roA[f] + (((uint32_t)(s * 32) + subA) ^ xoA[f]));

            // yl multiply on A fragments (regs 0,1 = k-lo pair; 2,3 = k-hi pair)
            const uint32_t koff = (uint32_t)(k * KC + s * 16) + ylo;
            const uint32_t ylA = *(const uint32_t*)(ylp + koff);
            const uint32_t ylB = *(const uint32_t*)(ylp + koff + 8);
#pragma unroll
            for (int f = 0; f < 2; f++) {
                afr[f][0] = hmul2u(afr[f][0], ylA);
                afr[f][1] = hmul2u(afr[f][1], ylA);
                afr[f][2] = hmul2u(afr[f][2], ylB);
                afr[f][3] = hmul2u(afr[f][3], ylB);
            }

            uint32_t bfr[8][2];
#pragma unroll
            for (int gp2 = 0; gp2 < 4; gp2++) {
                uint32_t t[4];
                ldm4(t, stb + roB[gp2] + (((uint32_t)(s * 32) + subB) ^ xoB[gp2]));
                bfr[gp2 * 2 + 0][0] = t[0]; bfr[gp2 * 2 + 0][1] = t[1];
                bfr[gp2 * 2 + 1][0] = t[2]; bfr[gp2 * 2 + 1][1] = t[3];
            }
#pragma unroll
            for (int f = 0; f < 2; f++)
#pragma unroll
                for (int g = 0; g < 8; g++)
                    mma16816(acc[f][g], afr[f], bfr[g]);
        }
    }

    // ---- epilogue: partial tile -> g_s[ks] ----
    float* dst = &g_s[ks][b][ych][0];
    const int cb  = warp_n * 64 + (lane & 3) * 2;
    const int rlo = lane >> 2;
#pragma unroll
    for (int f = 0; f < 2; f++) {
        const int rowb = warp_m * 32 + f * 16 + rlo;
#pragma unroll
        for (int g = 0; g < 8; g++) {
            const int cc2 = cb + g * 8;
            *(float2*)(dst + (size_t)rowb * GR + cc2)       = make_float2(acc[f][g][0], acc[f][g][1]);
            *(float2*)(dst + (size_t)(rowb + 8) * GR + cc2) = make_float2(acc[f][g][2], acc[f][g][3]);
        }
    }
}

// =====================  combine / normalize (fully parallel)  =====================
// grid = 1152: (b, ch, 16 m-blocks); thread handles 4 grid points of one channel
__global__ void __launch_bounds__(256)
rbf_comb(float* __restrict__ out)
{
    const int bx = blockIdx.x;
    const int b  = bx / 144;
    const int rr = bx % 144;
    const int ch = rr >> 4;
    const int m4 = (((rr & 15) << 8) + threadIdx.x) * 4;

    float4 dv = *(const float4*)&g_s[0][b][0][m4];
#pragma unroll
    for (int p = 1; p < KSPL; p++) {
        const float4 d = *(const float4*)&g_s[p][b][0][m4];
        dv.x += d.x; dv.y += d.y; dv.z += d.z; dv.w += d.w;
    }

    float* op = out + ((size_t)b * (YD + 1) + ch) * MM + m4;
    if (ch == 0) {
        *(float4*)op = dv;
        return;
    }
    float4 a = *(const float4*)&g_s[0][b][ch][m4];
#pragma unroll
    for (int p = 1; p < KSPL; p++) {
        const float4 d = *(const float4*)&g_s[p][b][ch][m4];
        a.x += d.x; a.y += d.y; a.z += d.z; a.w += d.w;
    }
    a.x *= rcpf(dv.x + 1e-5f);
    a.y *= rcpf(dv.y + 1e-5f);
    a.z *= rcpf(dv.z + 1e-5f);
    a.w *= rcpf(dv.w + 1e-5f);
    *(float4*)op = a;
}

extern "C" void kernel_launch(void* const* d_in, const int* in_sizes, int n_in,
                              void* d_out, int out_size)
{
    const float* xc    = (const float*)d_in[0];  // (8, 2048, 2)
    const float* yc    = (const float*)d_in[1];  // (8, 2048, 8)
    const float* gp    = (const float*)d_in[2];  // (1, 16384, 2)
    const float* sigma = (const float*)d_in[3];  // scalar
    float* out = (float*)d_out;                  // (8, 9, 128, 128)

    cudaFuncSetAttribute(rbf_gemm, cudaFuncAttributeMaxDynamicSharedMemorySize,
                         NSTAGE * STAGE);
    pre_all<<<400, 256>>>(xc, yc, gp, sigma);
    rbf_gemm<<<288, 256, NSTAGE * STAGE>>>();
    rbf_comb<<<1152, 256>>>(out);
}